// round 2
// baseline (speedup 1.0000x reference)
#include <cuda_runtime.h>
#include <cstdint>

// Problem constants (fixed shapes from reference)
#define IM_HW   16384          // 128*128 pixels
#define BC      64             // B*C = 2*32 channels
#define NB      10980          // 183*60 HT bins
#define NV      983040         // votes

// -------- persistent scratch (__device__ globals; no allocation) --------
__device__ float d_xt[IM_HW * BC];        // transposed image: [pix][bc]  (4 MB)
__device__ int   d_count[NB];
__device__ int   d_offs[NB + 1];
__device__ int   d_cursor[NB];
__device__ uint2 d_pairs[NV];             // per vote: (pix*256, bits(weight)) (7.9 MB)

// -------- 1. zero bin counters (must run every launch) --------
__global__ void zero_kernel() {
    int i = blockIdx.x * blockDim.x + threadIdx.x;
    if (i < NB) d_count[i] = 0;
}

// -------- 2. transpose image (b,c,pix) -> x_t[pix][bc] --------
__global__ void __launch_bounds__(256) transpose_kernel(const float* __restrict__ im) {
    __shared__ float tile[32][68];          // row pitch 272B = 17*16B -> float4-aligned
    int pixbase = blockIdx.x * 32;
    int t  = threadIdx.x;
    int tx = t & 31;        // pix within tile
    int ty = t >> 5;        // 8 channels per pass
    #pragma unroll
    for (int b0 = 0; b0 < BC; b0 += 8)
        tile[tx][b0 + ty] = im[(b0 + ty) * IM_HW + pixbase + tx];   // coalesced reads
    __syncthreads();
    int p  = t >> 3;            // 0..31 pix
    int c0 = (t & 7) * 8;       // 0..56 channel base
    float4* dst = (float4*)(d_xt + (pixbase + p) * BC + c0);
    dst[0] = *(float4*)&tile[p][c0];
    dst[1] = *(float4*)&tile[p][c0 + 4];    // full 32B sectors per lane
}

// -------- 3. histogram of ht indices --------
__global__ void count_kernel(const float* __restrict__ vm) {
    int v = blockIdx.x * blockDim.x + threadIdx.x;
    if (v < NV) {
        int ht = (int)vm[v * 3 + 1];
        atomicAdd(&d_count[ht], 1);
    }
}

// -------- 4. exclusive scan over 10980 counters (one block) --------
__global__ void __launch_bounds__(1024) scan_kernel() {
    __shared__ int wsum[32];
    const int ITEMS = 11;                  // 1024*11 = 11264 >= NB+1
    int t = threadIdx.x;
    int base = t * ITEMS;
    int loc[ITEMS];
    int s = 0;
    #pragma unroll
    for (int i = 0; i < ITEMS; i++) {
        int idx = base + i;
        int v = (idx < NB) ? d_count[idx] : 0;
        loc[i] = s;
        s += v;
    }
    int lane = t & 31, wid = t >> 5;
    int x = s;
    #pragma unroll
    for (int o = 1; o < 32; o <<= 1) {
        int y = __shfl_up_sync(0xffffffffu, x, o);
        if (lane >= o) x += y;
    }
    if (lane == 31) wsum[wid] = x;
    __syncthreads();
    if (wid == 0) {
        int y = wsum[lane];
        #pragma unroll
        for (int o = 1; o < 32; o <<= 1) {
            int z = __shfl_up_sync(0xffffffffu, y, o);
            if (lane >= o) y += z;
        }
        wsum[lane] = y;                    // inclusive per-warp sums
    }
    __syncthreads();
    int blockbase = (wid > 0) ? wsum[wid - 1] : 0;
    int texcl = blockbase + (x - s);       // this thread's exclusive prefix
    #pragma unroll
    for (int i = 0; i < ITEMS; i++) {
        int idx = base + i;
        if (idx <= NB) {
            int o = texcl + loc[i];
            d_offs[idx] = o;
            if (idx < NB) d_cursor[idx] = o;
        }
    }
}

// -------- 5. scatter votes into CSR slots --------
__global__ void fill_kernel(const float* __restrict__ vm) {
    int v = blockIdx.x * blockDim.x + threadIdx.x;
    if (v < NV) {
        float fp = vm[v * 3 + 0];
        float fh = vm[v * 3 + 1];
        float fw = vm[v * 3 + 2];
        int pix = (int)fp;
        int ht  = (int)fh;
        int pos = atomicAdd(&d_cursor[ht], 1);
        d_pairs[pos] = make_uint2((unsigned)(pix << 8), __float_as_uint(fw));
    }
}

// -------- 6. hot kernel: atomic-free segmented gather-reduce --------
// One warp per HT bin; lane l owns channels (2l, 2l+1). Per vote: one coalesced
// 256B warp read of x_t[pix][*], 2 FFMA/lane. Pairs load for iteration i+1 is
// prefetched so the dependent x-gather chain overlaps across iterations.
__global__ void __launch_bounds__(256) gather_kernel(float* __restrict__ out) {
    int warp = threadIdx.x >> 5;
    int lane = threadIdx.x & 31;
    int bin  = blockIdx.x * 8 + warp;
    if (bin >= NB) return;
    int s = d_offs[bin];
    int e = d_offs[bin + 1];
    const char* xb = (const char*)d_xt + lane * 8;
    float ax = 0.f, ay = 0.f;
    if (s < e) {
        uint2 pw = __ldg(&d_pairs[s]);
        #pragma unroll 4
        for (int i = s; i < e - 1; i++) {
            uint2 pw_next = __ldg(&d_pairs[i + 1]);     // prefetch next vote
            float2 xv = *(const float2*)(xb + pw.x);    // coalesced 256B per warp
            float w = __uint_as_float(pw.y);
            ax = fmaf(w, xv.x, ax);
            ay = fmaf(w, xv.y, ay);
            pw = pw_next;
        }
        float2 xv = *(const float2*)(xb + pw.x);
        float w = __uint_as_float(pw.y);
        ax = fmaf(w, xv.x, ax);
        ay = fmaf(w, xv.y, ay);
    }
    out[(2 * lane)     * NB + bin] = ax;
    out[(2 * lane + 1) * NB + bin] = ay;
}

// -------- launch --------
extern "C" void kernel_launch(void* const* d_in, const int* in_sizes, int n_in,
                              void* d_out, int out_size) {
    // Defensive input-order resolution: im has 1,048,576 elems; vm has 2,949,120.
    const float* im = (const float*)d_in[0];
    const float* vm = (const float*)d_in[1];
    if (in_sizes[0] == NV * 3) { im = (const float*)d_in[1]; vm = (const float*)d_in[0]; }
    float* out = (float*)d_out;

    zero_kernel<<<(NB + 255) / 256, 256>>>();
    transpose_kernel<<<IM_HW / 32, 256>>>(im);
    count_kernel<<<(NV + 255) / 256, 256>>>(vm);
    scan_kernel<<<1, 1024>>>();
    fill_kernel<<<(NV + 255) / 256, 256>>>(vm);
    gather_kernel<<<(NB + 7) / 8, 256>>>(out);
}

// round 3
// speedup vs baseline: 1.6550x; 1.6550x over previous
#include <cuda_runtime.h>
#include <cstdint>

#define IM_HW   16384          // 128*128 pixels
#define BC      64             // B*C channels
#define NB      10980          // 183*60 HT bins
#define NV      983040         // votes
#define CAP     256            // per-bin slot capacity (mean 89.5, sigma 9.4 -> 17 sigma)

// -------- persistent scratch (__device__ globals; no allocation) --------
__device__ float d_xt[IM_HW * BC];            // transposed image [pix][bc]   (4 MB)
__device__ int   d_cursor[NB];                // per-bin vote count
__device__ uint2 d_pairs[NB * CAP];           // (pix*256, bits(w)) per slot  (22.5 MB)
__device__ int   d_ovf_cnt;
__device__ uint4 d_ovf[NV];                   // overflow spill (pixoff, wbits, bin, 0)

// -------- 1. transpose image (b,c,pix) -> x_t[pix][bc], fused cursor zeroing --------
__global__ void __launch_bounds__(256) transpose_zero_kernel(const float* __restrict__ im) {
    // fused zeroing: 512 blocks; first 43 cover NB cursors, block 0 zeroes ovf count
    if (blockIdx.x < 43) {
        int i = blockIdx.x * 256 + threadIdx.x;
        if (i < NB) d_cursor[i] = 0;
        if (blockIdx.x == 0 && threadIdx.x == 0) d_ovf_cnt = 0;
    }
    __shared__ float tile[32][68];          // row pitch 272B = 17*16B -> float4-aligned
    int pixbase = blockIdx.x * 32;
    int t  = threadIdx.x;
    int tx = t & 31;
    int ty = t >> 5;
    #pragma unroll
    for (int b0 = 0; b0 < BC; b0 += 8)
        tile[tx][b0 + ty] = im[(b0 + ty) * IM_HW + pixbase + tx];   // coalesced
    __syncthreads();
    int p  = t >> 3;
    int c0 = (t & 7) * 8;
    float4* dst = (float4*)(d_xt + (pixbase + p) * BC + c0);
    dst[0] = *(float4*)&tile[p][c0];
    dst[1] = *(float4*)&tile[p][c0 + 4];
}

// -------- 2. single-pass fill into padded bins --------
__global__ void fill_kernel(const float* __restrict__ vm) {
    int v = blockIdx.x * blockDim.x + threadIdx.x;
    if (v >= NV) return;
    float fp = vm[v * 3 + 0];
    float fh = vm[v * 3 + 1];
    float fw = vm[v * 3 + 2];
    int pix = (int)fp;
    int bin = (int)fh;
    int pos = atomicAdd(&d_cursor[bin], 1);
    if (pos < CAP) {
        d_pairs[bin * CAP + pos] = make_uint2((unsigned)(pix << 8), __float_as_uint(fw));
    } else {
        int o = atomicAdd(&d_ovf_cnt, 1);
        d_ovf[o] = make_uint4((unsigned)(pix << 8), __float_as_uint(fw), (unsigned)bin, 0u);
    }
}

// -------- 3. hot kernel: atomic-free segmented gather-reduce --------
// One warp per bin. Half-warp h processes votes i%2==h; lane owns 4 channels
// (float4). Per warp-iteration: 2 votes, 2x256B coalesced x_t reads. Halves
// combined via shfl_xor(16). Output staged in smem for 32B-coalesced stores.
__global__ void __launch_bounds__(256) gather_kernel(float* __restrict__ out) {
    __shared__ float sout[BC][8];           // [channel][bin-in-block]
    int warp = threadIdx.x >> 5;
    int lane = threadIdx.x & 31;
    int bin0 = blockIdx.x * 8;
    int bin  = bin0 + warp;

    float4 acc = make_float4(0.f, 0.f, 0.f, 0.f);
    if (bin < NB) {
        int cnt = d_cursor[bin];
        if (cnt > CAP) cnt = CAP;
        const uint2* pp = d_pairs + (size_t)bin * CAP;
        int half = lane >> 4;               // 0 or 1
        const char* xb = (const char*)d_xt + (lane & 15) * 16;  // 4-channel byte offset
        #pragma unroll 4
        for (int i = half; i < cnt; i += 2) {
            uint2 pw = __ldg(&pp[i]);
            float4 xv = *(const float4*)(xb + pw.x);
            float w = __uint_as_float(pw.y);
            acc.x = fmaf(w, xv.x, acc.x);
            acc.y = fmaf(w, xv.y, acc.y);
            acc.z = fmaf(w, xv.z, acc.z);
            acc.w = fmaf(w, xv.w, acc.w);
        }
    }
    // combine the two half-warps (same channels, complementary votes)
    acc.x += __shfl_xor_sync(0xffffffffu, acc.x, 16);
    acc.y += __shfl_xor_sync(0xffffffffu, acc.y, 16);
    acc.z += __shfl_xor_sync(0xffffffffu, acc.z, 16);
    acc.w += __shfl_xor_sync(0xffffffffu, acc.w, 16);
    if (lane < 16) {
        int c = lane * 4;
        sout[c + 0][warp] = acc.x;
        sout[c + 1][warp] = acc.y;
        sout[c + 2][warp] = acc.z;
        sout[c + 3][warp] = acc.w;
    }
    __syncthreads();
    // coalesced write: thread t -> out[(t>>3)*NB + bin0 + (t&7)], 32B runs
    int c = threadIdx.x >> 3;
    int b = threadIdx.x & 7;
    if (bin0 + b < NB) {
        out[c * NB + bin0 + b]            = sout[c][b];
        out[(c + 32) * NB + bin0 + b]     = sout[c + 32][b];
    }
}

// -------- 4. overflow spill (empty in practice; correct if not) --------
__global__ void overflow_kernel(float* __restrict__ out) {
    int n = d_ovf_cnt;
    if (n <= 0) return;
    int total = n * BC;
    for (int k = blockIdx.x * blockDim.x + threadIdx.x; k < total;
         k += gridDim.x * blockDim.x) {
        int vi = k >> 6;
        int c  = k & 63;
        uint4 ov = d_ovf[vi];
        float w = __uint_as_float(ov.y);
        float x = *(const float*)((const char*)d_xt + ov.x + c * 4);
        atomicAdd(&out[c * NB + (int)ov.z], w * x);
    }
}

// -------- launch --------
extern "C" void kernel_launch(void* const* d_in, const int* in_sizes, int n_in,
                              void* d_out, int out_size) {
    const float* im = (const float*)d_in[0];
    const float* vm = (const float*)d_in[1];
    if (in_sizes[0] == NV * 3) { im = (const float*)d_in[1]; vm = (const float*)d_in[0]; }
    float* out = (float*)d_out;

    transpose_zero_kernel<<<IM_HW / 32, 256>>>(im);
    fill_kernel<<<(NV + 255) / 256, 256>>>(vm);
    gather_kernel<<<(NB + 7) / 8, 256>>>(out);
    overflow_kernel<<<16, 256>>>(out);
}

// round 5
// speedup vs baseline: 1.9477x; 1.1768x over previous
#include <cuda_runtime.h>
#include <cuda_fp16.h>
#include <cstdint>

#define IM_HW   16384          // 128*128 pixels
#define BC      64             // B*C channels
#define NB      10980          // 183*60 HT bins
#define NV      983040         // votes
#define CAP     256            // per-bin slot capacity (mean 89.5, sigma 9.4)

// bit-cast helpers (uint32 <-> __half2), compile to nothing
__device__ __forceinline__ __half2 u2h2(unsigned u) {
    union { unsigned u; __half2 h; } cvt; cvt.u = u; return cvt.h;
}
__device__ __forceinline__ unsigned h22u(__half2 h) {
    union { unsigned u; __half2 h; } cvt; cvt.h = h; return cvt.u;
}

// -------- persistent scratch (__device__ globals; no allocation) --------
__device__ uint2 d_xh[IM_HW * 16];            // fp16 image [pix][64ch] = 128B/row (2 MB)
__device__ int   d_cursor[NB];                // per-bin vote count
__device__ uint2 d_pairs[NB * CAP];           // (pix*128, bits(w_fp32)) per slot (22.5 MB)
__device__ int   d_ovf_cnt;
__device__ uint4 d_ovf[4096];                 // overflow spill (pixoff, wbits, bin, 0)

// -------- 1. transpose + fp16 convert, fused cursor zeroing --------
__global__ void __launch_bounds__(256) transpose_zero_kernel(const float* __restrict__ im) {
    if (blockIdx.x < 43) {
        int i = blockIdx.x * 256 + threadIdx.x;
        if (i < NB) d_cursor[i] = 0;
        if (blockIdx.x == 0 && threadIdx.x == 0) d_ovf_cnt = 0;
    }
    __shared__ float tile[32][68];            // pitch 272B -> float4-aligned rows
    int pixbase = blockIdx.x * 32;
    int t  = threadIdx.x;
    int tx = t & 31;
    int ty = t >> 5;
    #pragma unroll
    for (int b0 = 0; b0 < BC; b0 += 8)
        tile[tx][b0 + ty] = im[(b0 + ty) * IM_HW + pixbase + tx];   // coalesced
    __syncthreads();
    int p  = t >> 3;            // pix in tile
    int c0 = (t & 7) * 8;       // channel base (8 channels -> 16B fp16)
    float4 a = *(float4*)&tile[p][c0];
    float4 b = *(float4*)&tile[p][c0 + 4];
    uint4 hv;
    hv.x = h22u(__float22half2_rn(make_float2(a.x, a.y)));
    hv.y = h22u(__float22half2_rn(make_float2(a.z, a.w)));
    hv.z = h22u(__float22half2_rn(make_float2(b.x, b.y)));
    hv.w = h22u(__float22half2_rn(make_float2(b.z, b.w)));
    *(uint4*)((char*)d_xh + (pixbase + p) * 128 + c0 * 2) = hv;
}

// -------- 2. single-pass fill into padded bins --------
__global__ void fill_kernel(const float* __restrict__ vm) {
    int v = blockIdx.x * blockDim.x + threadIdx.x;
    if (v >= NV) return;
    float fp = vm[v * 3 + 0];
    float fh = vm[v * 3 + 1];
    float fw = vm[v * 3 + 2];
    int pix = (int)fp;
    int bin = (int)fh;
    int pos = atomicAdd(&d_cursor[bin], 1);
    if (pos < CAP) {
        d_pairs[bin * CAP + pos] = make_uint2((unsigned)(pix << 7), __float_as_uint(fw));
    } else {
        int o = atomicAdd(&d_ovf_cnt, 1);
        if (o < 4096)
            d_ovf[o] = make_uint4((unsigned)(pix << 7), __float_as_uint(fw), (unsigned)bin, 0u);
    }
}

// -------- 3. hot kernel: atomic-free segmented gather-reduce (fp16 x) --------
// One warp per bin. Half-warp h processes votes i%2==h; lane owns 4 channels
// (8B fp16). Per warp-iteration: 2 votes, 2x128B coalesced x_h reads, fp32 acc.
// Overflow spill handled inline (count==0 in practice). Output staged in smem.
__global__ void __launch_bounds__(256) gather_kernel(float* __restrict__ out) {
    __shared__ float sout[BC][8];             // [channel][bin-in-block]
    int warp = threadIdx.x >> 5;
    int lane = threadIdx.x & 31;
    int bin0 = blockIdx.x * 8;
    int bin  = bin0 + warp;

    float4 acc = make_float4(0.f, 0.f, 0.f, 0.f);
    if (bin < NB) {
        int cnt = d_cursor[bin];
        if (cnt > CAP) cnt = CAP;
        const uint2* pp = d_pairs + (size_t)bin * CAP;
        int half = lane >> 4;                 // 0 or 1
        const char* xb = (const char*)d_xh + (lane & 15) * 8;   // 4 fp16 channels
        #pragma unroll 4
        for (int i = half; i < cnt; i += 2) {
            uint2 pw = __ldg(&pp[i]);
            uint2 xv = *(const uint2*)(xb + pw.x);              // 128B per half-warp
            float2 f0 = __half22float2(u2h2(xv.x));
            float2 f1 = __half22float2(u2h2(xv.y));
            float w = __uint_as_float(pw.y);
            acc.x = fmaf(w, f0.x, acc.x);
            acc.y = fmaf(w, f0.y, acc.y);
            acc.z = fmaf(w, f1.x, acc.z);
            acc.w = fmaf(w, f1.y, acc.w);
        }
        // inline overflow spill (empty in practice, correct if not)
        int novf = d_ovf_cnt;
        if (novf > 4096) novf = 4096;
        for (int j = 0; j < novf; j++) {
            uint4 ov = d_ovf[j];
            if ((int)ov.z == bin && half == 0) {
                uint2 xv = *(const uint2*)(xb + ov.x);
                float2 f0 = __half22float2(u2h2(xv.x));
                float2 f1 = __half22float2(u2h2(xv.y));
                float w = __uint_as_float(ov.y);
                acc.x = fmaf(w, f0.x, acc.x);
                acc.y = fmaf(w, f0.y, acc.y);
                acc.z = fmaf(w, f1.x, acc.z);
                acc.w = fmaf(w, f1.y, acc.w);
            }
        }
    }
    // combine the two half-warps
    acc.x += __shfl_xor_sync(0xffffffffu, acc.x, 16);
    acc.y += __shfl_xor_sync(0xffffffffu, acc.y, 16);
    acc.z += __shfl_xor_sync(0xffffffffu, acc.z, 16);
    acc.w += __shfl_xor_sync(0xffffffffu, acc.w, 16);
    if (lane < 16) {
        int c = lane * 4;
        sout[c + 0][warp] = acc.x;
        sout[c + 1][warp] = acc.y;
        sout[c + 2][warp] = acc.z;
        sout[c + 3][warp] = acc.w;
    }
    __syncthreads();
    // coalesced write: thread t -> out[(t>>3)*NB + bin0 + (t&7)]
    int c = threadIdx.x >> 3;
    int b = threadIdx.x & 7;
    if (bin0 + b < NB) {
        out[c * NB + bin0 + b]        = sout[c][b];
        out[(c + 32) * NB + bin0 + b] = sout[c + 32][b];
    }
}

// -------- launch --------
extern "C" void kernel_launch(void* const* d_in, const int* in_sizes, int n_in,
                              void* d_out, int out_size) {
    const float* im = (const float*)d_in[0];
    const float* vm = (const float*)d_in[1];
    if (in_sizes[0] == NV * 3) { im = (const float*)d_in[1]; vm = (const float*)d_in[0]; }
    float* out = (float*)d_out;

    transpose_zero_kernel<<<IM_HW / 32, 256>>>(im);
    fill_kernel<<<(NV + 255) / 256, 256>>>(vm);
    gather_kernel<<<(NB + 7) / 8, 256>>>(out);
}

// round 6
// speedup vs baseline: 1.9560x; 1.0043x over previous
#include <cuda_runtime.h>
#include <cuda_fp16.h>
#include <cstdint>

#define IM_HW   16384          // 128*128 pixels
#define BC      64             // B*C channels
#define NB      10980          // 183*60 HT bins
#define NV      983040         // votes (= 3840*256 exactly)
#define CAP     256            // per-bin capacity (mean 89.5, sigma 9.4 -> 17 sigma)
#define TBLK    512            // transpose blocks in fused prep kernel

__device__ __forceinline__ __half2 u2h2(unsigned u) {
    union { unsigned u; __half2 h; } c; c.u = u; return c.h;
}
__device__ __forceinline__ unsigned h22u(__half2 h) {
    union { unsigned u; __half2 h; } c; c.h = h; return c.u;
}

// -------- persistent scratch (__device__ globals; zero-initialized) --------
__device__ uint4 d_xh[IM_HW * 8];             // fp16 image [pix][64ch] = 128B/row (2 MB)
__device__ int   d_cursor[NB];                // per-bin count; left zeroed by gather
__device__ uint2 d_pairs[NB * CAP];           // (pix*128, bits(w_fp32)) per slot (22.5 MB)
__device__ int   d_ovf_cnt;                   // left zeroed by gather
__device__ uint4 d_ovf[4096];                 // overflow spill (pixoff, wbits, bin, 0)

// -------- 1. fused prep: transpose+fp16 (blocks 0..511) || fill (blocks 512+) --------
__global__ void __launch_bounds__(256) prep_kernel(const float* __restrict__ im,
                                                   const float* __restrict__ vm) {
    if (blockIdx.x < TBLK) {
        // ---- transpose image (b,c,pix) -> x_h[pix][bc] fp16 ----
        __shared__ float tile[32][68];        // pitch 272B -> float4-aligned rows
        int pixbase = blockIdx.x * 32;
        int t  = threadIdx.x;
        int tx = t & 31;
        int ty = t >> 5;
        #pragma unroll
        for (int b0 = 0; b0 < BC; b0 += 8)
            tile[tx][b0 + ty] = im[(b0 + ty) * IM_HW + pixbase + tx];   // coalesced
        __syncthreads();
        int p  = t >> 3;            // pix in tile
        int c0 = (t & 7) * 8;       // channel base (8 ch -> 16B fp16)
        float4 a = *(float4*)&tile[p][c0];
        float4 b = *(float4*)&tile[p][c0 + 4];
        uint4 hv;
        hv.x = h22u(__float22half2_rn(make_float2(a.x, a.y)));
        hv.y = h22u(__float22half2_rn(make_float2(a.z, a.w)));
        hv.z = h22u(__float22half2_rn(make_float2(b.x, b.y)));
        hv.w = h22u(__float22half2_rn(make_float2(b.z, b.w)));
        *(uint4*)((char*)d_xh + (pixbase + p) * 128 + c0 * 2) = hv;
    } else {
        // ---- single-pass fill into padded bins ----
        int v = (blockIdx.x - TBLK) * 256 + threadIdx.x;   // < NV by construction
        float fp = __ldg(&vm[v * 3 + 0]);
        float fh = __ldg(&vm[v * 3 + 1]);
        float fw = __ldg(&vm[v * 3 + 2]);
        int pix = (int)fp;
        int bin = (int)fh;
        int pos = atomicAdd(&d_cursor[bin], 1);
        if (pos < CAP) {
            d_pairs[bin * CAP + pos] = make_uint2((unsigned)(pix << 7), __float_as_uint(fw));
        } else {
            int o = atomicAdd(&d_ovf_cnt, 1);
            if (o < 4096)
                d_ovf[o] = make_uint4((unsigned)(pix << 7), __float_as_uint(fw),
                                      (unsigned)bin, 0u);
        }
    }
}

// -------- 2. hot kernel: atomic-free segmented gather-reduce (fp16 x) --------
// One warp per bin; quarter-warp q handles votes i%4==q; lane owns 8 channels
// (16B LDG.128). 4 votes / warp-iteration, 128B/vote from L2-resident x_h,
// fp32 accumulation. Resets cursors/ovf for the next graph replay.
__global__ void __launch_bounds__(256) gather_kernel(float* __restrict__ out) {
    __shared__ float sout[BC][8];             // [channel][bin-in-block]
    int warp = threadIdx.x >> 5;
    int lane = threadIdx.x & 31;
    int bin0 = blockIdx.x * 8;
    int bin  = bin0 + warp;

    float acc[8] = {0.f, 0.f, 0.f, 0.f, 0.f, 0.f, 0.f, 0.f};
    if (bin < NB) {
        int cnt  = d_cursor[bin];
        int novf = d_ovf_cnt;                 // read before any reset (0 in practice)
        if (cnt > CAP) cnt = CAP;
        const uint2* pp = d_pairs + (size_t)bin * CAP;
        int q = lane >> 3;                    // 0..3
        const char* xb = (const char*)d_xh + (lane & 7) * 16;   // 8 fp16 channels
        #pragma unroll 4
        for (int i = q; i < cnt; i += 4) {
            uint2 pw = __ldg(&pp[i]);                       // 4 consecutive pairs/warp
            uint4 xv = *(const uint4*)(xb + pw.x);          // 128B per quarter-warp
            float w = __uint_as_float(pw.y);
            float2 f0 = __half22float2(u2h2(xv.x));
            float2 f1 = __half22float2(u2h2(xv.y));
            float2 f2 = __half22float2(u2h2(xv.z));
            float2 f3 = __half22float2(u2h2(xv.w));
            acc[0] = fmaf(w, f0.x, acc[0]);
            acc[1] = fmaf(w, f0.y, acc[1]);
            acc[2] = fmaf(w, f1.x, acc[2]);
            acc[3] = fmaf(w, f1.y, acc[3]);
            acc[4] = fmaf(w, f2.x, acc[4]);
            acc[5] = fmaf(w, f2.y, acc[5]);
            acc[6] = fmaf(w, f3.x, acc[6]);
            acc[7] = fmaf(w, f3.y, acc[7]);
        }
        // inline overflow spill (statistically unreachable; correct if hit)
        if (novf > 4096) novf = 4096;
        for (int j = 0; j < novf; j++) {
            uint4 ov = d_ovf[j];
            if ((int)ov.z == bin && q == 0) {
                uint4 xv = *(const uint4*)(xb + ov.x);
                float w = __uint_as_float(ov.y);
                float2 f0 = __half22float2(u2h2(xv.x));
                float2 f1 = __half22float2(u2h2(xv.y));
                float2 f2 = __half22float2(u2h2(xv.z));
                float2 f3 = __half22float2(u2h2(xv.w));
                acc[0] = fmaf(w, f0.x, acc[0]);
                acc[1] = fmaf(w, f0.y, acc[1]);
                acc[2] = fmaf(w, f1.x, acc[2]);
                acc[3] = fmaf(w, f1.y, acc[3]);
                acc[4] = fmaf(w, f2.x, acc[4]);
                acc[5] = fmaf(w, f2.y, acc[5]);
                acc[6] = fmaf(w, f3.x, acc[6]);
                acc[7] = fmaf(w, f3.y, acc[7]);
            }
        }
        if (lane == 0) d_cursor[bin] = 0;     // reset for next replay (sole reader)
    }
    if (blockIdx.x == 0 && threadIdx.x == 0) d_ovf_cnt = 0;   // benign (stays 0)

    // combine the four quarter-warps
    #pragma unroll
    for (int k = 0; k < 8; k++) {
        acc[k] += __shfl_xor_sync(0xffffffffu, acc[k], 8);
        acc[k] += __shfl_xor_sync(0xffffffffu, acc[k], 16);
    }
    if (lane < 8) {
        #pragma unroll
        for (int k = 0; k < 8; k++) sout[lane * 8 + k][warp] = acc[k];
    }
    __syncthreads();
    // coalesced write: thread t -> out[(t>>3)*NB + bin0 + (t&7)]
    int c = threadIdx.x >> 3;
    int b = threadIdx.x & 7;
    if (bin0 + b < NB) {
        out[c * NB + bin0 + b]        = sout[c][b];
        out[(c + 32) * NB + bin0 + b] = sout[c + 32][b];
    }
}

// -------- launch --------
extern "C" void kernel_launch(void* const* d_in, const int* in_sizes, int n_in,
                              void* d_out, int out_size) {
    const float* im = (const float*)d_in[0];
    const float* vm = (const float*)d_in[1];
    if (in_sizes[0] == NV * 3) { im = (const float*)d_in[1]; vm = (const float*)d_in[0]; }
    float* out = (float*)d_out;

    prep_kernel<<<TBLK + NV / 256, 256>>>(im, vm);
    gather_kernel<<<(NB + 7) / 8, 256>>>(out);
}